// round 1
// baseline (speedup 1.0000x reference)
#include <cuda_runtime.h>
#include <math.h>

// Problem dims
#define L_ 16
#define H_ 8
#define D_ 768
#define DH_ 96
#define F_ 2048
#define V_ 32000
#define B_ 2
#define S_ 1024
#define BS_ (B_ * S_)
#define EPS_ 1e-6f

// Scratch (static device globals; no allocation allowed)
__device__ float g_x[BS_ * D_];    // residual stream
__device__ float g_xn[BS_ * D_];   // normed activations
__device__ float g_q[BS_ * D_];
__device__ float g_k[BS_ * D_];
__device__ float g_v[BS_ * D_];
__device__ float g_o[BS_ * D_];
__device__ float g_att[(long long)B_ * H_ * S_ * S_];  // 64 MB
__device__ float g_ffn[BS_ * F_];                      // 16 MB

// ---------------------------------------------------------------------------
// Fused embedding + RMSNorm:  x = rmsnorm(tok_emb[tok] + pos_emb[s]) * w
// ---------------------------------------------------------------------------
__global__ void embed_norm_kernel(const int* __restrict__ tok,
                                  const float* __restrict__ tok_emb,
                                  const float* __restrict__ pos_emb,
                                  const float* __restrict__ w) {
    int row = blockIdx.x;        // 0..BS-1
    int s = row % S_;
    int t = tok[row];
    __shared__ float buf[D_];
    __shared__ float red[256];
    float ss = 0.f;
    for (int d = threadIdx.x; d < D_; d += 256) {
        float v = tok_emb[(long long)t * D_ + d] + pos_emb[(long long)s * D_ + d];
        buf[d] = v;
        ss += v * v;
    }
    red[threadIdx.x] = ss;
    __syncthreads();
    for (int o = 128; o > 0; o >>= 1) {
        if (threadIdx.x < o) red[threadIdx.x] += red[threadIdx.x + o];
        __syncthreads();
    }
    float inv = rsqrtf(red[0] / (float)D_ + EPS_);
    for (int d = threadIdx.x; d < D_; d += 256)
        g_x[(long long)row * D_ + d] = buf[d] * inv * w[d];
}

// ---------------------------------------------------------------------------
// RMSNorm: out[row] = in[row] * rsqrt(mean(in^2)+eps) * w
// ---------------------------------------------------------------------------
__global__ void rmsnorm_kernel(const float* __restrict__ in, float* __restrict__ out,
                               const float* __restrict__ w, int n) {
    long long row = blockIdx.x;
    const float* x = in + row * n;
    float ss = 0.f;
    for (int d = threadIdx.x; d < n; d += 256) { float v = x[d]; ss += v * v; }
    __shared__ float red[256];
    red[threadIdx.x] = ss;
    __syncthreads();
    for (int o = 128; o > 0; o >>= 1) {
        if (threadIdx.x < o) red[threadIdx.x] += red[threadIdx.x + o];
        __syncthreads();
    }
    float inv = rsqrtf(red[0] / (float)n + EPS_);
    float* y = out + row * n;
    for (int d = threadIdx.x; d < n; d += 256) y[d] = x[d] * inv * w[d];
}

// ---------------------------------------------------------------------------
// Generic batched GEMM: C = alpha * A @ B (+ residual R) (optional gelu)
//   A: [M,K] row-major, lda
//   B: [K,N] row-major (TRANSB=false) or [N,K] row-major (TRANSB=true)
//   Per-batch (grid.z = z) pointer offsets: (z/hdiv)*sO + (z%hdiv)*sI
//   Residual R (if non-null) uses C's offsets/ldc.
// Tile 64x64x16, 256 threads, 4x4 micro-tile, padded SMEM.
// ---------------------------------------------------------------------------
__device__ __forceinline__ float gelu_tanh(float x) {
    return 0.5f * x * (1.f + tanhf(0.7978845608028654f * (x + 0.044715f * x * x * x)));
}

template <bool TRANSB>
__global__ void gemm_kernel(
    const float* __restrict__ A, int lda, long long saO, long long saI,
    const float* __restrict__ Bp, int ldb, long long sbO, long long sbI,
    float* __restrict__ C, int ldc, long long scO, long long scI,
    const float* __restrict__ R,
    int M, int N, int K, float alpha, int gelu_flag, int hdiv)
{
    int z = blockIdx.z;
    int zo = z / hdiv, zi = z % hdiv;
    A  += (long long)zo * saO + (long long)zi * saI;
    Bp += (long long)zo * sbO + (long long)zi * sbI;
    long long co = (long long)zo * scO + (long long)zi * scI;
    C += co;
    if (R) R += co;

    __shared__ float As[16][68];   // padded: keeps 16B alignment, kills conflicts
    __shared__ float Bs[16][68];

    int tid = threadIdx.x;
    int tx = tid & 15, ty = tid >> 4;
    int m0 = blockIdx.y * 64, n0 = blockIdx.x * 64;

    float acc[4][4] = {};

    for (int k0 = 0; k0 < K; k0 += 16) {
        // Load A tile 64x16 (store transposed As[k][m])
        #pragma unroll
        for (int i = 0; i < 4; i++) {
            int e = tid + i * 256;
            int m = e >> 4, kk = e & 15;
            float v = 0.f;
            if (m0 + m < M && k0 + kk < K)
                v = A[(long long)(m0 + m) * lda + (k0 + kk)];
            As[kk][m] = v;
        }
        // Load B tile 16x64
        #pragma unroll
        for (int i = 0; i < 4; i++) {
            int e = tid + i * 256;
            float v = 0.f;
            if (!TRANSB) {
                int kk = e >> 6, n = e & 63;
                if (n0 + n < N && k0 + kk < K)
                    v = Bp[(long long)(k0 + kk) * ldb + (n0 + n)];
                Bs[kk][n] = v;
            } else {
                int n = e >> 4, kk = e & 15;
                if (n0 + n < N && k0 + kk < K)
                    v = Bp[(long long)(n0 + n) * ldb + (k0 + kk)];
                Bs[kk][n] = v;
            }
        }
        __syncthreads();
        #pragma unroll
        for (int kk = 0; kk < 16; kk++) {
            float4 a = *(const float4*)&As[kk][ty * 4];
            float4 b = *(const float4*)&Bs[kk][tx * 4];
            acc[0][0] += a.x * b.x; acc[0][1] += a.x * b.y; acc[0][2] += a.x * b.z; acc[0][3] += a.x * b.w;
            acc[1][0] += a.y * b.x; acc[1][1] += a.y * b.y; acc[1][2] += a.y * b.z; acc[1][3] += a.y * b.w;
            acc[2][0] += a.z * b.x; acc[2][1] += a.z * b.y; acc[2][2] += a.z * b.z; acc[2][3] += a.z * b.w;
            acc[3][0] += a.w * b.x; acc[3][1] += a.w * b.y; acc[3][2] += a.w * b.z; acc[3][3] += a.w * b.w;
        }
        __syncthreads();
    }

    #pragma unroll
    for (int i = 0; i < 4; i++) {
        int row = m0 + ty * 4 + i;
        if (row >= M) continue;
        #pragma unroll
        for (int j = 0; j < 4; j++) {
            int col = n0 + tx * 4 + j;
            if (col >= N) continue;
            float v = acc[i][j] * alpha;
            if (R) v += R[(long long)row * ldc + col];
            if (gelu_flag) v = gelu_tanh(v);
            C[(long long)row * ldc + col] = v;
        }
    }
}

// ---------------------------------------------------------------------------
// Causal softmax over g_att rows. blockIdx.x = (b*H + h)*S + i
// Valid columns: j <= i; columns j > i zeroed.
// ---------------------------------------------------------------------------
__global__ void softmax_causal_kernel(float* __restrict__ att) {
    long long idx = blockIdx.x;
    int i = (int)(idx % S_);
    float* row = att + idx * S_;
    int n = i + 1;

    __shared__ float red[256];
    float mx = -INFINITY;
    for (int j = threadIdx.x; j < n; j += 256) mx = fmaxf(mx, row[j]);
    red[threadIdx.x] = mx;
    __syncthreads();
    for (int o = 128; o > 0; o >>= 1) {
        if (threadIdx.x < o) red[threadIdx.x] = fmaxf(red[threadIdx.x], red[threadIdx.x + o]);
        __syncthreads();
    }
    mx = red[0];
    __syncthreads();

    float sum = 0.f;
    for (int j = threadIdx.x; j < n; j += 256) {
        float e = expf(row[j] - mx);
        row[j] = e;
        sum += e;
    }
    red[threadIdx.x] = sum;
    __syncthreads();
    for (int o = 128; o > 0; o >>= 1) {
        if (threadIdx.x < o) red[threadIdx.x] += red[threadIdx.x + o];
        __syncthreads();
    }
    float inv = 1.f / red[0];

    for (int j = threadIdx.x; j < n; j += 256) row[j] *= inv;
    for (int j = n + threadIdx.x; j < S_; j += 256) row[j] = 0.f;
}

// ---------------------------------------------------------------------------
// Host-side launch helpers
// ---------------------------------------------------------------------------
static void launch_gemm(bool transB,
                        const float* A, int lda, long long saO, long long saI,
                        const float* Bp, int ldb, long long sbO, long long sbI,
                        float* C, int ldc, long long scO, long long scI,
                        const float* R, int M, int N, int K,
                        float alpha, int gelu_flag, int hdiv, int batch)
{
    dim3 grid((N + 63) / 64, (M + 63) / 64, batch);
    if (transB)
        gemm_kernel<true><<<grid, 256>>>(A, lda, saO, saI, Bp, ldb, sbO, sbI,
                                         C, ldc, scO, scI, R, M, N, K, alpha, gelu_flag, hdiv);
    else
        gemm_kernel<false><<<grid, 256>>>(A, lda, saO, saI, Bp, ldb, sbO, sbI,
                                          C, ldc, scO, scI, R, M, N, K, alpha, gelu_flag, hdiv);
}

extern "C" void kernel_launch(void* const* d_in, const int* in_sizes, int n_in,
                              void* d_out, int out_size) {
    const int*   tok         = (const int*)d_in[0];
    const float* tok_emb     = (const float*)d_in[1];
    const float* pos_emb     = (const float*)d_in[2];
    const float* pos_norm_w  = (const float*)d_in[3];
    const float* attn_norm_w = (const float*)d_in[4];
    const float* wq          = (const float*)d_in[5];
    const float* wk          = (const float*)d_in[6];
    const float* wv          = (const float*)d_in[7];
    const float* wo          = (const float*)d_in[8];
    const float* ffn_norm_w  = (const float*)d_in[9];
    const float* w1          = (const float*)d_in[10];
    const float* w2          = (const float*)d_in[11];
    const float* out_norm_w  = (const float*)d_in[12];
    const float* out_w       = (const float*)d_in[13];
    float* out = (float*)d_out;

    float *x, *xn, *q, *k, *v, *o, *att, *ffn;
    cudaGetSymbolAddress((void**)&x,   g_x);
    cudaGetSymbolAddress((void**)&xn,  g_xn);
    cudaGetSymbolAddress((void**)&q,   g_q);
    cudaGetSymbolAddress((void**)&k,   g_k);
    cudaGetSymbolAddress((void**)&v,   g_v);
    cudaGetSymbolAddress((void**)&o,   g_o);
    cudaGetSymbolAddress((void**)&att, g_att);
    cudaGetSymbolAddress((void**)&ffn, g_ffn);

    const float scale = 0.102062072615966f;  // DH^-0.5 = 1/sqrt(96)
    const long long SS = (long long)S_ * S_;

    // x = rmsnorm(tok_emb[tok] + pos_emb[:S]) * pos_norm_w
    embed_norm_kernel<<<BS_, 256>>>(tok, tok_emb, pos_emb, pos_norm_w);

    for (int l = 0; l < L_; l++) {
        const float* lwq = wq + (long long)l * D_ * D_;
        const float* lwk = wk + (long long)l * D_ * D_;
        const float* lwv = wv + (long long)l * D_ * D_;
        const float* lwo = wo + (long long)l * D_ * D_;
        const float* lw1 = w1 + (long long)l * D_ * F_;
        const float* lw2 = w2 + (long long)l * F_ * D_;

        // xn = rmsnorm(x, attn_norm_w[l])
        rmsnorm_kernel<<<BS_, 256>>>(x, xn, attn_norm_w + (long long)l * D_, D_);

        // q/k/v = xn @ W  [BS,768]
        launch_gemm(false, xn, D_, 0, 0, lwq, D_, 0, 0, q, D_, 0, 0,
                    nullptr, BS_, D_, D_, 1.f, 0, 1, 1);
        launch_gemm(false, xn, D_, 0, 0, lwk, D_, 0, 0, k, D_, 0, 0,
                    nullptr, BS_, D_, D_, 1.f, 0, 1, 1);
        launch_gemm(false, xn, D_, 0, 0, lwv, D_, 0, 0, v, D_, 0, 0,
                    nullptr, BS_, D_, D_, 1.f, 0, 1, 1);

        // scores[b,h] = scale * Q_h @ K_h^T   (batched over z = b*H + h)
        launch_gemm(true,
                    q, D_, (long long)S_ * D_, DH_,
                    k, D_, (long long)S_ * D_, DH_,
                    att, S_, (long long)H_ * SS, SS,
                    nullptr, S_, S_, DH_, scale, 0, H_, B_ * H_);

        // causal softmax in-place
        softmax_causal_kernel<<<B_ * H_ * S_, 256>>>(att);

        // o[b,:,h,:] = probs @ V_h
        launch_gemm(false,
                    att, S_, (long long)H_ * SS, SS,
                    v, D_, (long long)S_ * D_, DH_,
                    o, D_, (long long)S_ * D_, DH_,
                    nullptr, S_, DH_, S_, 1.f, 0, H_, B_ * H_);

        // x = x + o @ wo
        launch_gemm(false, o, D_, 0, 0, lwo, D_, 0, 0, x, D_, 0, 0,
                    x, BS_, D_, D_, 1.f, 0, 1, 1);

        // xn = rmsnorm(x, ffn_norm_w[l])
        rmsnorm_kernel<<<BS_, 256>>>(x, xn, ffn_norm_w + (long long)l * D_, D_);

        // ffn = gelu(xn @ w1)
        launch_gemm(false, xn, D_, 0, 0, lw1, F_, 0, 0, ffn, F_, 0, 0,
                    nullptr, BS_, F_, D_, 1.f, 1, 1, 1);

        // x = x + ffn @ w2
        launch_gemm(false, ffn, F_, 0, 0, lw2, D_, 0, 0, x, D_, 0, 0,
                    x, BS_, D_, F_, 1.f, 0, 1, 1);
    }

    // logits = rmsnorm(x, out_norm_w) @ out_w
    rmsnorm_kernel<<<BS_, 256>>>(x, xn, out_norm_w, D_);
    launch_gemm(false, xn, D_, 0, 0, out_w, V_, 0, 0, out, V_, 0, 0,
                nullptr, BS_, V_, D_, 1.f, 0, 1, 1);
}

// round 2
// speedup vs baseline: 1.8828x; 1.8828x over previous
#include <cuda_runtime.h>
#include <math.h>

// Problem dims
#define L_ 16
#define H_ 8
#define D_ 768
#define DH_ 96
#define F_ 2048
#define V_ 32000
#define B_ 2
#define S_ 1024
#define BS_ (B_ * S_)
#define EPS_ 1e-6f

// Scratch (static device globals; no allocation allowed)
__device__ float g_x[BS_ * D_];    // residual stream
__device__ float g_xn[BS_ * D_];   // normed activations
__device__ float g_q[BS_ * D_];
__device__ float g_k[BS_ * D_];
__device__ float g_v[BS_ * D_];
__device__ float g_o[BS_ * D_];
__device__ float g_att[(long long)B_ * H_ * S_ * S_];  // 64 MB
__device__ float g_ffn[BS_ * F_];                      // 16 MB

// ---------------------------------------------------------------------------
// Fused embedding + RMSNorm
// ---------------------------------------------------------------------------
__global__ void embed_norm_kernel(const int* __restrict__ tok,
                                  const float* __restrict__ tok_emb,
                                  const float* __restrict__ pos_emb,
                                  const float* __restrict__ w) {
    int row = blockIdx.x;
    int s = row % S_;
    int t = tok[row];
    __shared__ float buf[D_];
    __shared__ float red[256];
    float ss = 0.f;
    for (int d = threadIdx.x; d < D_; d += 256) {
        float v = tok_emb[(long long)t * D_ + d] + pos_emb[(long long)s * D_ + d];
        buf[d] = v;
        ss += v * v;
    }
    red[threadIdx.x] = ss;
    __syncthreads();
    for (int o = 128; o > 0; o >>= 1) {
        if (threadIdx.x < o) red[threadIdx.x] += red[threadIdx.x + o];
        __syncthreads();
    }
    float inv = rsqrtf(red[0] / (float)D_ + EPS_);
    for (int d = threadIdx.x; d < D_; d += 256)
        g_x[(long long)row * D_ + d] = buf[d] * inv * w[d];
}

// ---------------------------------------------------------------------------
// RMSNorm
// ---------------------------------------------------------------------------
__global__ void rmsnorm_kernel(const float* __restrict__ in, float* __restrict__ out,
                               const float* __restrict__ w, int n) {
    long long row = blockIdx.x;
    const float* x = in + row * n;
    float ss = 0.f;
    for (int d = threadIdx.x; d < n; d += 256) { float v = x[d]; ss += v * v; }
    __shared__ float red[256];
    red[threadIdx.x] = ss;
    __syncthreads();
    for (int o = 128; o > 0; o >>= 1) {
        if (threadIdx.x < o) red[threadIdx.x] += red[threadIdx.x + o];
        __syncthreads();
    }
    float inv = rsqrtf(red[0] / (float)n + EPS_);
    float* y = out + row * n;
    for (int d = threadIdx.x; d < n; d += 256) y[d] = x[d] * inv * w[d];
}

// ---------------------------------------------------------------------------
// TF32 tensor-core batched GEMM: C = alpha * A @ B (+R) (opt gelu)
// Block tile 128x128x32, 256 threads, warp tile 32x64 (m16n8k8 tf32 MMA)
// ---------------------------------------------------------------------------
__device__ __forceinline__ unsigned f2tf32(float x) {
    unsigned r;
    asm("cvt.rna.tf32.f32 %0, %1;" : "=r"(r) : "f"(x));
    return r;
}

__device__ __forceinline__ void mma_tf32(float* d, const unsigned* a, const unsigned* b) {
    asm volatile("mma.sync.aligned.m16n8k8.row.col.f32.tf32.tf32.f32 "
                 "{%0,%1,%2,%3}, {%4,%5,%6,%7}, {%8,%9}, {%0,%1,%2,%3};"
                 : "+f"(d[0]), "+f"(d[1]), "+f"(d[2]), "+f"(d[3])
                 : "r"(a[0]), "r"(a[1]), "r"(a[2]), "r"(a[3]),
                   "r"(b[0]), "r"(b[1]));
}

__device__ __forceinline__ float gelu_tanh(float x) {
    return 0.5f * x * (1.f + tanhf(0.7978845608028654f * (x + 0.044715f * x * x * x)));
}

// SMEM stride 136 floats: 544B (16B aligned rows), bank step per k-row = 8
#define SSTR 136

template <bool TRANSB>
__global__ void __launch_bounds__(256) gemm_tc_kernel(
    const float* __restrict__ A, int lda, long long saO, long long saI,
    const float* __restrict__ Bp, int ldb, long long sbO, long long sbI,
    float* __restrict__ C, int ldc, long long scO, long long scI,
    const float* __restrict__ R,
    int M, int N, int K, float alpha, int gelu_flag, int hdiv)
{
    int z = blockIdx.z;
    int zo = z / hdiv, zi = z % hdiv;
    A  += (long long)zo * saO + (long long)zi * saI;
    Bp += (long long)zo * sbO + (long long)zi * sbI;
    long long co = (long long)zo * scO + (long long)zi * scI;
    C += co;
    if (R) R += co;

    __shared__ __align__(16) unsigned As[32][SSTR];  // k-major [kk][m]
    __shared__ __align__(16) unsigned Bs[32][SSTR];  // k-major [kk][n]

    int tid = threadIdx.x;
    int warp = tid >> 5, lane = tid & 31;
    int g = lane >> 2, t = lane & 3;          // groupID / threadID_in_group
    int mwarp = (warp & 3) * 32;              // warp grid 4 (m) x 2 (n)
    int nwarp = (warp >> 2) * 64;
    int m0 = blockIdx.y * 128, n0 = blockIdx.x * 128;

    float acc[2][8][4];
    #pragma unroll
    for (int i = 0; i < 2; i++)
        #pragma unroll
        for (int j = 0; j < 8; j++)
            #pragma unroll
            for (int r = 0; r < 4; r++) acc[i][j][r] = 0.f;

    for (int k0 = 0; k0 < K; k0 += 32) {
        // ---- Stage A tile 128x32 (transpose to k-major). f = row + 128*kq
        #pragma unroll
        for (int i = 0; i < 4; i++) {
            int f = tid + i * 256;
            int row = f & 127, kq = f >> 7;
            float4 v = make_float4(0.f, 0.f, 0.f, 0.f);
            if (m0 + row < M)
                v = *(const float4*)&A[(long long)(m0 + row) * lda + (k0 + kq * 4)];
            As[kq * 4 + 0][row] = f2tf32(v.x);
            As[kq * 4 + 1][row] = f2tf32(v.y);
            As[kq * 4 + 2][row] = f2tf32(v.z);
            As[kq * 4 + 3][row] = f2tf32(v.w);
        }
        // ---- Stage B tile 32x128
        if (!TRANSB) {
            // B row-major [K][N]: f = nq + 32*kk, STS.128 along n
            #pragma unroll
            for (int i = 0; i < 4; i++) {
                int f = tid + i * 256;
                int kk = f >> 5, nq = f & 31;
                float4 v = make_float4(0.f, 0.f, 0.f, 0.f);
                if (n0 + nq * 4 + 3 < N)
                    v = *(const float4*)&Bp[(long long)(k0 + kk) * ldb + (n0 + nq * 4)];
                uint4 u = make_uint4(f2tf32(v.x), f2tf32(v.y), f2tf32(v.z), f2tf32(v.w));
                *(uint4*)&Bs[kk][nq * 4] = u;
            }
        } else {
            // B row-major [N][K]: f = n + 128*kq, scatter into k-major
            #pragma unroll
            for (int i = 0; i < 4; i++) {
                int f = tid + i * 256;
                int n = f & 127, kq = f >> 7;
                float4 v = make_float4(0.f, 0.f, 0.f, 0.f);
                if (n0 + n < N)
                    v = *(const float4*)&Bp[(long long)(n0 + n) * ldb + (k0 + kq * 4)];
                Bs[kq * 4 + 0][n] = f2tf32(v.x);
                Bs[kq * 4 + 1][n] = f2tf32(v.y);
                Bs[kq * 4 + 2][n] = f2tf32(v.z);
                Bs[kq * 4 + 3][n] = f2tf32(v.w);
            }
        }
        __syncthreads();

        // ---- 4 k-slices of 8
        #pragma unroll
        for (int ks = 0; ks < 4; ks++) {
            int krow = ks * 8 + t;
            unsigned af[2][4];
            #pragma unroll
            for (int mt = 0; mt < 2; mt++) {
                int m = mwarp + mt * 16 + g;
                af[mt][0] = As[krow][m];
                af[mt][1] = As[krow][m + 8];
                af[mt][2] = As[krow + 4][m];
                af[mt][3] = As[krow + 4][m + 8];
            }
            unsigned bf[8][2];
            #pragma unroll
            for (int nt = 0; nt < 8; nt++) {
                int n = nwarp + nt * 8 + g;
                bf[nt][0] = Bs[krow][n];
                bf[nt][1] = Bs[krow + 4][n];
            }
            #pragma unroll
            for (int mt = 0; mt < 2; mt++)
                #pragma unroll
                for (int nt = 0; nt < 8; nt++)
                    mma_tf32(acc[mt][nt], af[mt], bf[nt]);
        }
        __syncthreads();
    }

    // ---- Epilogue
    #pragma unroll
    for (int mt = 0; mt < 2; mt++) {
        #pragma unroll
        for (int nt = 0; nt < 8; nt++) {
            #pragma unroll
            for (int r = 0; r < 4; r++) {
                int row = m0 + mwarp + mt * 16 + g + ((r & 2) ? 8 : 0);
                int col = n0 + nwarp + nt * 8 + t * 2 + (r & 1);
                if (row < M && col < N) {
                    float v = acc[mt][nt][r] * alpha;
                    if (R) v += R[(long long)row * ldc + col];
                    if (gelu_flag) v = gelu_tanh(v);
                    C[(long long)row * ldc + col] = v;
                }
            }
        }
    }
}

// ---------------------------------------------------------------------------
// Causal softmax
// ---------------------------------------------------------------------------
__global__ void softmax_causal_kernel(float* __restrict__ att) {
    long long idx = blockIdx.x;
    int i = (int)(idx % S_);
    float* row = att + idx * S_;
    int n = i + 1;

    __shared__ float red[256];
    float mx = -INFINITY;
    for (int j = threadIdx.x; j < n; j += 256) mx = fmaxf(mx, row[j]);
    red[threadIdx.x] = mx;
    __syncthreads();
    for (int o = 128; o > 0; o >>= 1) {
        if (threadIdx.x < o) red[threadIdx.x] = fmaxf(red[threadIdx.x], red[threadIdx.x + o]);
        __syncthreads();
    }
    mx = red[0];
    __syncthreads();

    float sum = 0.f;
    for (int j = threadIdx.x; j < n; j += 256) {
        float e = expf(row[j] - mx);
        row[j] = e;
        sum += e;
    }
    red[threadIdx.x] = sum;
    __syncthreads();
    for (int o = 128; o > 0; o >>= 1) {
        if (threadIdx.x < o) red[threadIdx.x] += red[threadIdx.x + o];
        __syncthreads();
    }
    float inv = 1.f / red[0];

    for (int j = threadIdx.x; j < n; j += 256) row[j] *= inv;
    for (int j = n + threadIdx.x; j < S_; j += 256) row[j] = 0.f;
}

// ---------------------------------------------------------------------------
// Host-side launch helper
// ---------------------------------------------------------------------------
static void launch_gemm(bool transB,
                        const float* A, int lda, long long saO, long long saI,
                        const float* Bp, int ldb, long long sbO, long long sbI,
                        float* C, int ldc, long long scO, long long scI,
                        const float* R, int M, int N, int K,
                        float alpha, int gelu_flag, int hdiv, int batch)
{
    dim3 grid((N + 127) / 128, (M + 127) / 128, batch);
    if (transB)
        gemm_tc_kernel<true><<<grid, 256>>>(A, lda, saO, saI, Bp, ldb, sbO, sbI,
                                            C, ldc, scO, scI, R, M, N, K, alpha, gelu_flag, hdiv);
    else
        gemm_tc_kernel<false><<<grid, 256>>>(A, lda, saO, saI, Bp, ldb, sbO, sbI,
                                             C, ldc, scO, scI, R, M, N, K, alpha, gelu_flag, hdiv);
}

extern "C" void kernel_launch(void* const* d_in, const int* in_sizes, int n_in,
                              void* d_out, int out_size) {
    const int*   tok         = (const int*)d_in[0];
    const float* tok_emb     = (const float*)d_in[1];
    const float* pos_emb     = (const float*)d_in[2];
    const float* pos_norm_w  = (const float*)d_in[3];
    const float* attn_norm_w = (const float*)d_in[4];
    const float* wq          = (const float*)d_in[5];
    const float* wk          = (const float*)d_in[6];
    const float* wv          = (const float*)d_in[7];
    const float* wo          = (const float*)d_in[8];
    const float* ffn_norm_w  = (const float*)d_in[9];
    const float* w1          = (const float*)d_in[10];
    const float* w2          = (const float*)d_in[11];
    const float* out_norm_w  = (const float*)d_in[12];
    const float* out_w       = (const float*)d_in[13];
    float* out = (float*)d_out;

    float *x, *xn, *q, *k, *v, *o, *att, *ffn;
    cudaGetSymbolAddress((void**)&x,   g_x);
    cudaGetSymbolAddress((void**)&xn,  g_xn);
    cudaGetSymbolAddress((void**)&q,   g_q);
    cudaGetSymbolAddress((void**)&k,   g_k);
    cudaGetSymbolAddress((void**)&v,   g_v);
    cudaGetSymbolAddress((void**)&o,   g_o);
    cudaGetSymbolAddress((void**)&att, g_att);
    cudaGetSymbolAddress((void**)&ffn, g_ffn);

    const float scale = 0.102062072615966f;  // 1/sqrt(96)
    const long long SS = (long long)S_ * S_;

    embed_norm_kernel<<<BS_, 256>>>(tok, tok_emb, pos_emb, pos_norm_w);

    for (int l = 0; l < L_; l++) {
        const float* lwq = wq + (long long)l * D_ * D_;
        const float* lwk = wk + (long long)l * D_ * D_;
        const float* lwv = wv + (long long)l * D_ * D_;
        const float* lwo = wo + (long long)l * D_ * D_;
        const float* lw1 = w1 + (long long)l * D_ * F_;
        const float* lw2 = w2 + (long long)l * F_ * D_;

        rmsnorm_kernel<<<BS_, 256>>>(x, xn, attn_norm_w + (long long)l * D_, D_);

        launch_gemm(false, xn, D_, 0, 0, lwq, D_, 0, 0, q, D_, 0, 0,
                    nullptr, BS_, D_, D_, 1.f, 0, 1, 1);
        launch_gemm(false, xn, D_, 0, 0, lwk, D_, 0, 0, k, D_, 0, 0,
                    nullptr, BS_, D_, D_, 1.f, 0, 1, 1);
        launch_gemm(false, xn, D_, 0, 0, lwv, D_, 0, 0, v, D_, 0, 0,
                    nullptr, BS_, D_, D_, 1.f, 0, 1, 1);

        // scores[b,h] = scale * Q_h @ K_h^T
        launch_gemm(true,
                    q, D_, (long long)S_ * D_, DH_,
                    k, D_, (long long)S_ * D_, DH_,
                    att, S_, (long long)H_ * SS, SS,
                    nullptr, S_, S_, DH_, scale, 0, H_, B_ * H_);

        softmax_causal_kernel<<<B_ * H_ * S_, 256>>>(att);

        // o[b,:,h,:] = probs @ V_h
        launch_gemm(false,
                    att, S_, (long long)H_ * SS, SS,
                    v, D_, (long long)S_ * D_, DH_,
                    o, D_, (long long)S_ * D_, DH_,
                    nullptr, S_, DH_, S_, 1.f, 0, H_, B_ * H_);

        // x = x + o @ wo
        launch_gemm(false, o, D_, 0, 0, lwo, D_, 0, 0, x, D_, 0, 0,
                    x, BS_, D_, D_, 1.f, 0, 1, 1);

        rmsnorm_kernel<<<BS_, 256>>>(x, xn, ffn_norm_w + (long long)l * D_, D_);

        // ffn = gelu(xn @ w1)
        launch_gemm(false, xn, D_, 0, 0, lw1, F_, 0, 0, ffn, F_, 0, 0,
                    nullptr, BS_, F_, D_, 1.f, 1, 1, 1);

        // x = x + ffn @ w2
        launch_gemm(false, ffn, F_, 0, 0, lw2, D_, 0, 0, x, D_, 0, 0,
                    x, BS_, D_, F_, 1.f, 0, 1, 1);
    }

    rmsnorm_kernel<<<BS_, 256>>>(x, xn, out_norm_w, D_);
    launch_gemm(false, xn, D_, 0, 0, out_w, V_, 0, 0, out, V_, 0, 0,
                nullptr, BS_, V_, D_, 1.f, 0, 1, 1);
}

// round 3
// speedup vs baseline: 2.7166x; 1.4429x over previous
#include <cuda_runtime.h>
#include <math.h>

// Problem dims
#define L_ 16
#define H_ 8
#define D_ 768
#define DH_ 96
#define F_ 2048
#define V_ 32000
#define B_ 2
#define S_ 1024
#define BS_ (B_ * S_)
#define EPS_ 1e-6f
#define PIPE 3

// Scratch (static device globals; padded so unpredicated tile loads stay in-bounds)
__device__ float g_x[BS_ * D_ + 256];
__device__ float g_xn[BS_ * D_ + 256];
__device__ float g_q[BS_ * D_ + 256];
__device__ float g_k[BS_ * D_ + 256];
__device__ float g_v[BS_ * D_ + 256];
__device__ float g_o[BS_ * D_ + 256];
__device__ float g_att[(long long)B_ * H_ * S_ * S_ + 256];
__device__ float g_ffn[BS_ * F_ + 256];

struct MultiPtr {
    const float* B[3];
    float* C[3];
};

// ---------------------------------------------------------------------------
// Fused embedding + RMSNorm
// ---------------------------------------------------------------------------
__global__ void embed_norm_kernel(const int* __restrict__ tok,
                                  const float* __restrict__ tok_emb,
                                  const float* __restrict__ pos_emb,
                                  const float* __restrict__ w) {
    int row = blockIdx.x;
    int s = row % S_;
    int t = tok[row];
    __shared__ float buf[D_];
    __shared__ float red[256];
    float ss = 0.f;
    for (int d = threadIdx.x; d < D_; d += 256) {
        float v = tok_emb[(long long)t * D_ + d] + pos_emb[(long long)s * D_ + d];
        buf[d] = v;
        ss += v * v;
    }
    red[threadIdx.x] = ss;
    __syncthreads();
    for (int o = 128; o > 0; o >>= 1) {
        if (threadIdx.x < o) red[threadIdx.x] += red[threadIdx.x + o];
        __syncthreads();
    }
    float inv = rsqrtf(red[0] / (float)D_ + EPS_);
    for (int d = threadIdx.x; d < D_; d += 256)
        g_x[(long long)row * D_ + d] = buf[d] * inv * w[d];
}

// ---------------------------------------------------------------------------
// RMSNorm
// ---------------------------------------------------------------------------
__global__ void rmsnorm_kernel(const float* __restrict__ in, float* __restrict__ out,
                               const float* __restrict__ w, int n) {
    long long row = blockIdx.x;
    const float* x = in + row * n;
    float ss = 0.f;
    for (int d = threadIdx.x; d < n; d += 256) { float v = x[d]; ss += v * v; }
    __shared__ float red[256];
    red[threadIdx.x] = ss;
    __syncthreads();
    for (int o = 128; o > 0; o >>= 1) {
        if (threadIdx.x < o) red[threadIdx.x] += red[threadIdx.x + o];
        __syncthreads();
    }
    float inv = rsqrtf(red[0] / (float)n + EPS_);
    float* y = out + row * n;
    for (int d = threadIdx.x; d < n; d += 256) y[d] = x[d] * inv * w[d];
}

// ---------------------------------------------------------------------------
// TF32 tensor-core GEMM with cp.async 3-stage pipeline
// Block tile BM x 128 x 32, 256 threads.
// A SMEM: [BM][36] row-major (floats). B SMEM: TRANSB ? [128][36] : [32][132].
// ---------------------------------------------------------------------------
__device__ __forceinline__ unsigned f2tf32(float x) {
    unsigned r;
    asm("cvt.rna.tf32.f32 %0, %1;" : "=r"(r) : "f"(x));
    return r;
}

__device__ __forceinline__ void cp16(float* dst, const float* src) {
    unsigned d = (unsigned)__cvta_generic_to_shared(dst);
    asm volatile("cp.async.cg.shared.global [%0], [%1], 16;" :: "r"(d), "l"(src));
}

__device__ __forceinline__ void mma_tf32(float* d, const unsigned* a, const unsigned* b) {
    asm volatile("mma.sync.aligned.m16n8k8.row.col.f32.tf32.tf32.f32 "
                 "{%0,%1,%2,%3}, {%4,%5,%6,%7}, {%8,%9}, {%0,%1,%2,%3};"
                 : "+f"(d[0]), "+f"(d[1]), "+f"(d[2]), "+f"(d[3])
                 : "r"(a[0]), "r"(a[1]), "r"(a[2]), "r"(a[3]),
                   "r"(b[0]), "r"(b[1]));
}

__device__ __forceinline__ float gelu_tanh(float x) {
    return 0.5f * x * (1.f + tanhf(0.7978845608028654f * (x + 0.044715f * x * x * x)));
}

#define BFL 4608  // floats reserved for B tile per stage (max of 128*36, 32*132)

template <bool TRANSB, int BM>
__global__ void __launch_bounds__(256) gemm_tc_async(
    const float* __restrict__ A, int lda, long long saO, long long saI,
    const float* __restrict__ Bp, int ldb, long long sbO, long long sbI,
    float* __restrict__ C, int ldc, long long scO, long long scI,
    const float* __restrict__ R,
    int M, int N, int K, float alpha, int gelu_flag, int hdiv,
    MultiPtr P, int nmulti)
{
    constexpr int WM = BM / 32;      // warps along m
    constexpr int WN = 8 / WM;       // warps along n
    constexpr int WTN = 128 / WN;    // warp n-tile
    constexpr int NT = WTN / 8;      // n MMA tiles per warp
    constexpr int STAGE = BM * 36 + BFL;

    extern __shared__ float smf[];

    int z = blockIdx.z;
    if (nmulti > 1) {
        Bp = P.B[z];
        C = P.C[z];
    } else {
        int zo = z / hdiv, zi = z % hdiv;
        A  += (long long)zo * saO + (long long)zi * saI;
        Bp += (long long)zo * sbO + (long long)zi * sbI;
        long long co = (long long)zo * scO + (long long)zi * scI;
        C += co;
        if (R) R += co;
    }

    int tid = threadIdx.x;
    int warp = tid >> 5, lane = tid & 31;
    int g = lane >> 2, t = lane & 3;
    int mwarp = (warp % WM) * 32;
    int nwarp = (warp / WM) * WTN;
    int m0 = blockIdx.y * BM, n0 = blockIdx.x * 128;

    float acc[2][NT][4];
    #pragma unroll
    for (int i = 0; i < 2; i++)
        #pragma unroll
        for (int j = 0; j < NT; j++)
            #pragma unroll
            for (int r = 0; r < 4; r++) acc[i][j][r] = 0.f;

    const int KT = K >> 5;

    // --- staging: natural-layout cp.async into stage buffer
    auto stage = [&](int kt, int sbuf) {
        float* Asf = smf + sbuf * STAGE;
        float* Bsf = Asf + BM * 36;
        int k0 = kt * 32;
        #pragma unroll
        for (int i = 0; i < BM / 32; i++) {
            int f = tid + i * 256;
            int row = f >> 3, ch = f & 7;
            cp16(Asf + row * 36 + ch * 4,
                 A + (long long)(m0 + row) * lda + k0 + ch * 4);
        }
        if (TRANSB) {
            #pragma unroll
            for (int i = 0; i < 4; i++) {
                int f = tid + i * 256;
                int row = f >> 3, ch = f & 7;
                cp16(Bsf + row * 36 + ch * 4,
                     Bp + (long long)(n0 + row) * ldb + k0 + ch * 4);
            }
        } else {
            #pragma unroll
            for (int i = 0; i < 4; i++) {
                int f = tid + i * 256;
                int kk = f >> 5, ch = f & 31;
                cp16(Bsf + kk * 132 + ch * 4,
                     Bp + (long long)(k0 + kk) * ldb + n0 + ch * 4);
            }
        }
        asm volatile("cp.async.commit_group;" ::: "memory");
    };

    for (int s = 0; s < PIPE - 1 && s < KT; s++) stage(s, s);

    for (int kt = 0; kt < KT; kt++) {
        if (kt == KT - 1) asm volatile("cp.async.wait_group 0;" ::: "memory");
        else              asm volatile("cp.async.wait_group %0;" :: "n"(PIPE - 2) : "memory");
        __syncthreads();

        int nk = kt + PIPE - 1;
        if (nk < KT) stage(nk, nk % PIPE);

        const float* Asf = smf + (kt % PIPE) * STAGE;
        const float* Bsf = Asf + BM * 36;

        #pragma unroll
        for (int ks = 0; ks < 4; ks++) {
            int krow = ks * 8 + t;
            unsigned af[2][4];
            #pragma unroll
            for (int mt = 0; mt < 2; mt++) {
                int m = mwarp + mt * 16 + g;
                af[mt][0] = f2tf32(Asf[m * 36 + krow]);
                af[mt][1] = f2tf32(Asf[(m + 8) * 36 + krow]);
                af[mt][2] = f2tf32(Asf[m * 36 + krow + 4]);
                af[mt][3] = f2tf32(Asf[(m + 8) * 36 + krow + 4]);
            }
            unsigned bf[NT][2];
            #pragma unroll
            for (int nt = 0; nt < NT; nt++) {
                int n = nwarp + nt * 8 + g;
                if (TRANSB) {
                    bf[nt][0] = f2tf32(Bsf[n * 36 + krow]);
                    bf[nt][1] = f2tf32(Bsf[n * 36 + krow + 4]);
                } else {
                    bf[nt][0] = f2tf32(Bsf[krow * 132 + n]);
                    bf[nt][1] = f2tf32(Bsf[(krow + 4) * 132 + n]);
                }
            }
            #pragma unroll
            for (int mt = 0; mt < 2; mt++)
                #pragma unroll
                for (int nt = 0; nt < NT; nt++)
                    mma_tf32(acc[mt][nt], af[mt], bf[nt]);
        }
        __syncthreads();
    }

    // --- Epilogue
    #pragma unroll
    for (int mt = 0; mt < 2; mt++) {
        #pragma unroll
        for (int nt = 0; nt < NT; nt++) {
            #pragma unroll
            for (int r = 0; r < 4; r++) {
                int row = m0 + mwarp + mt * 16 + g + ((r & 2) ? 8 : 0);
                int col = n0 + nwarp + nt * 8 + t * 2 + (r & 1);
                if (row < M && col < N) {
                    float v = acc[mt][nt][r] * alpha;
                    if (R) v += R[(long long)row * ldc + col];
                    if (gelu_flag) v = gelu_tanh(v);
                    C[(long long)row * ldc + col] = v;
                }
            }
        }
    }
}

// ---------------------------------------------------------------------------
// Causal softmax
// ---------------------------------------------------------------------------
__global__ void softmax_causal_kernel(float* __restrict__ att) {
    long long idx = blockIdx.x;
    int i = (int)(idx % S_);
    float* row = att + idx * S_;
    int n = i + 1;

    __shared__ float red[256];
    float mx = -INFINITY;
    for (int j = threadIdx.x; j < n; j += 256) mx = fmaxf(mx, row[j]);
    red[threadIdx.x] = mx;
    __syncthreads();
    for (int o = 128; o > 0; o >>= 1) {
        if (threadIdx.x < o) red[threadIdx.x] = fmaxf(red[threadIdx.x], red[threadIdx.x + o]);
        __syncthreads();
    }
    mx = red[0];
    __syncthreads();

    float sum = 0.f;
    for (int j = threadIdx.x; j < n; j += 256) {
        float e = expf(row[j] - mx);
        row[j] = e;
        sum += e;
    }
    red[threadIdx.x] = sum;
    __syncthreads();
    for (int o = 128; o > 0; o >>= 1) {
        if (threadIdx.x < o) red[threadIdx.x] += red[threadIdx.x + o];
        __syncthreads();
    }
    float inv = 1.f / red[0];

    for (int j = threadIdx.x; j < n; j += 256) row[j] *= inv;
    for (int j = n + threadIdx.x; j < S_; j += 256) row[j] = 0.f;
}

// ---------------------------------------------------------------------------
// Host launch helpers
// ---------------------------------------------------------------------------
template <bool TB, int BM>
static void run_gemm(dim3 grid,
                     const float* A, int lda, long long saO, long long saI,
                     const float* Bp, int ldb, long long sbO, long long sbI,
                     float* C, int ldc, long long scO, long long scI,
                     const float* R, int M, int N, int K,
                     float alpha, int gelu_flag, int hdiv,
                     MultiPtr mp, int nmulti)
{
    size_t smem = (size_t)PIPE * (BM * 36 + BFL) * sizeof(float);
    cudaFuncSetAttribute(gemm_tc_async<TB, BM>,
                         cudaFuncAttributeMaxDynamicSharedMemorySize, (int)smem);
    gemm_tc_async<TB, BM><<<grid, 256, smem>>>(A, lda, saO, saI, Bp, ldb, sbO, sbI,
                                               C, ldc, scO, scI, R, M, N, K,
                                               alpha, gelu_flag, hdiv, mp, nmulti);
}

extern "C" void kernel_launch(void* const* d_in, const int* in_sizes, int n_in,
                              void* d_out, int out_size) {
    const int*   tok         = (const int*)d_in[0];
    const float* tok_emb     = (const float*)d_in[1];
    const float* pos_emb     = (const float*)d_in[2];
    const float* pos_norm_w  = (const float*)d_in[3];
    const float* attn_norm_w = (const float*)d_in[4];
    const float* wq          = (const float*)d_in[5];
    const float* wk          = (const float*)d_in[6];
    const float* wv          = (const float*)d_in[7];
    const float* wo          = (const float*)d_in[8];
    const float* ffn_norm_w  = (const float*)d_in[9];
    const float* w1          = (const float*)d_in[10];
    const float* w2          = (const float*)d_in[11];
    const float* out_norm_w  = (const float*)d_in[12];
    const float* out_w       = (const float*)d_in[13];
    float* out = (float*)d_out;

    float *x, *xn, *q, *k, *v, *o, *att, *ffn;
    cudaGetSymbolAddress((void**)&x,   g_x);
    cudaGetSymbolAddress((void**)&xn,  g_xn);
    cudaGetSymbolAddress((void**)&q,   g_q);
    cudaGetSymbolAddress((void**)&k,   g_k);
    cudaGetSymbolAddress((void**)&v,   g_v);
    cudaGetSymbolAddress((void**)&o,   g_o);
    cudaGetSymbolAddress((void**)&att, g_att);
    cudaGetSymbolAddress((void**)&ffn, g_ffn);

    const float scale = 0.102062072615966f;  // 1/sqrt(96)
    const long long SS = (long long)S_ * S_;
    MultiPtr mp0 = {};

    embed_norm_kernel<<<BS_, 256>>>(tok, tok_emb, pos_emb, pos_norm_w);

    for (int l = 0; l < L_; l++) {
        const float* lwq = wq + (long long)l * D_ * D_;
        const float* lwk = wk + (long long)l * D_ * D_;
        const float* lwv = wv + (long long)l * D_ * D_;
        const float* lwo = wo + (long long)l * D_ * D_;
        const float* lw1 = w1 + (long long)l * D_ * F_;
        const float* lw2 = w2 + (long long)l * F_ * D_;

        rmsnorm_kernel<<<BS_, 256>>>(x, xn, attn_norm_w + (long long)l * D_, D_);

        // fused QKV: one launch, grid.z selects weight/output
        MultiPtr mq;
        mq.B[0] = lwq; mq.B[1] = lwk; mq.B[2] = lwv;
        mq.C[0] = q;   mq.C[1] = k;   mq.C[2] = v;
        run_gemm<false, 128>(dim3(6, 16, 3),
                             xn, D_, 0, 0, lwq, D_, 0, 0, q, D_, 0, 0,
                             nullptr, BS_, D_, D_, 1.f, 0, 1, mq, 3);

        // scores[b,h] = scale * Q_h @ K_h^T
        run_gemm<true, 128>(dim3(8, 8, 16),
                            q, D_, (long long)S_ * D_, DH_,
                            k, D_, (long long)S_ * D_, DH_,
                            att, S_, (long long)H_ * SS, SS,
                            nullptr, S_, S_, DH_, scale, 0, H_, mp0, 1);

        softmax_causal_kernel<<<B_ * H_ * S_, 256>>>(att);

        // o[b,:,h,:] = probs @ V_h
        run_gemm<false, 64>(dim3(1, 16, 16),
                            att, S_, (long long)H_ * SS, SS,
                            v, D_, (long long)S_ * D_, DH_,
                            o, D_, (long long)S_ * D_, DH_,
                            nullptr, S_, DH_, S_, 1.f, 0, H_, mp0, 1);

        // x = x + o @ wo
        run_gemm<false, 64>(dim3(6, 32, 1),
                            o, D_, 0, 0, lwo, D_, 0, 0, x, D_, 0, 0,
                            x, BS_, D_, D_, 1.f, 0, 1, mp0, 1);

        rmsnorm_kernel<<<BS_, 256>>>(x, xn, ffn_norm_w + (long long)l * D_, D_);

        // ffn = gelu(xn @ w1)
        run_gemm<false, 128>(dim3(16, 16, 1),
                             xn, D_, 0, 0, lw1, F_, 0, 0, ffn, F_, 0, 0,
                             nullptr, BS_, F_, D_, 1.f, 1, 1, mp0, 1);

        // x = x + ffn @ w2
        run_gemm<false, 64>(dim3(6, 32, 1),
                            ffn, F_, 0, 0, lw2, D_, 0, 0, x, D_, 0, 0,
                            x, BS_, D_, F_, 1.f, 0, 1, mp0, 1);
    }

    rmsnorm_kernel<<<BS_, 256>>>(x, xn, out_norm_w, D_);
    run_gemm<false, 128>(dim3(250, 16, 1),
                         xn, D_, 0, 0, out_w, V_, 0, 0, out, V_, 0, 0,
                         nullptr, BS_, V_, D_, 1.f, 0, 1, mp0, 1);
}

// round 4
// speedup vs baseline: 2.9008x; 1.0678x over previous
#include <cuda_runtime.h>
#include <math.h>

// Problem dims
#define L_ 16
#define H_ 8
#define D_ 768
#define DH_ 96
#define F_ 2048
#define V_ 32000
#define B_ 2
#define S_ 1024
#define BS_ (B_ * S_)
#define EPS_ 1e-6f
#define PIPE 3

// Activation scratch (padded so unpredicated tile loads stay in-bounds)
__device__ float g_x[BS_ * D_ + 256];
__device__ float g_xn[BS_ * D_ + 256];
__device__ float g_q[BS_ * D_ + 256];
__device__ float g_k[BS_ * D_ + 256];
__device__ float g_v[BS_ * D_ + 256];
__device__ float g_o[BS_ * D_ + 256];
__device__ float g_att[(long long)B_ * H_ * S_ * S_ + 256];
__device__ float g_ffn[BS_ * F_ + 256];

// TF32-rounded weight copies (rounded once per launch; values exactly tf32)
__device__ float g_cwq[L_ * D_ * D_];
__device__ float g_cwk[L_ * D_ * D_];
__device__ float g_cwv[L_ * D_ * D_];
__device__ float g_cwo[L_ * D_ * D_];
__device__ float g_cw1[(long long)L_ * D_ * F_];
__device__ float g_cw2[(long long)L_ * F_ * D_];
__device__ float g_cow[(long long)D_ * V_];

struct MultiPtr {
    const float* B[3];
    float* C[3];
};

__device__ __forceinline__ unsigned f2tf32(float x) {
    unsigned r;
    asm("cvt.rna.tf32.f32 %0, %1;" : "=r"(r) : "f"(x));
    return r;
}
__device__ __forceinline__ float roundtf(float x) { return __uint_as_float(f2tf32(x)); }

// ---------------------------------------------------------------------------
// Weight -> TF32 rounding (vectorized, grid-stride)
// ---------------------------------------------------------------------------
__global__ void cvt_tf32_kernel(const float4* __restrict__ in, float4* __restrict__ out,
                                long long n4) {
    long long i = (long long)blockIdx.x * blockDim.x + threadIdx.x;
    long long stride = (long long)gridDim.x * blockDim.x;
    for (; i < n4; i += stride) {
        float4 v = in[i];
        v.x = roundtf(v.x); v.y = roundtf(v.y); v.z = roundtf(v.z); v.w = roundtf(v.w);
        out[i] = v;
    }
}

// ---------------------------------------------------------------------------
// Fused embedding + RMSNorm (residual stream: full fp32)
// ---------------------------------------------------------------------------
__global__ void embed_norm_kernel(const int* __restrict__ tok,
                                  const float* __restrict__ tok_emb,
                                  const float* __restrict__ pos_emb,
                                  const float* __restrict__ w) {
    int row = blockIdx.x;
    int s = row % S_;
    int t = tok[row];
    __shared__ float buf[D_];
    __shared__ float red[256];
    float ss = 0.f;
    for (int d = threadIdx.x; d < D_; d += 256) {
        float v = tok_emb[(long long)t * D_ + d] + pos_emb[(long long)s * D_ + d];
        buf[d] = v;
        ss += v * v;
    }
    red[threadIdx.x] = ss;
    __syncthreads();
    for (int o = 128; o > 0; o >>= 1) {
        if (threadIdx.x < o) red[threadIdx.x] += red[threadIdx.x + o];
        __syncthreads();
    }
    float inv = rsqrtf(red[0] / (float)D_ + EPS_);
    for (int d = threadIdx.x; d < D_; d += 256)
        g_x[(long long)row * D_ + d] = buf[d] * inv * w[d];
}

// ---------------------------------------------------------------------------
// RMSNorm; output rounded to tf32 (always feeds a GEMM A operand)
// ---------------------------------------------------------------------------
__global__ void rmsnorm_kernel(const float* __restrict__ in, float* __restrict__ out,
                               const float* __restrict__ w, int n) {
    long long row = blockIdx.x;
    const float* x = in + row * n;
    float ss = 0.f;
    for (int d = threadIdx.x; d < n; d += 256) { float v = x[d]; ss += v * v; }
    __shared__ float red[256];
    red[threadIdx.x] = ss;
    __syncthreads();
    for (int o = 128; o > 0; o >>= 1) {
        if (threadIdx.x < o) red[threadIdx.x] += red[threadIdx.x + o];
        __syncthreads();
    }
    float inv = rsqrtf(red[0] / (float)n + EPS_);
    float* y = out + row * n;
    for (int d = threadIdx.x; d < n; d += 256) y[d] = roundtf(x[d] * inv * w[d]);
}

// ---------------------------------------------------------------------------
// TF32 tensor-core GEMM, cp.async 3-stage pipeline. Operands pre-rounded to
// tf32 -> inner loop is pure LDS + MMA (no conversions).
// ---------------------------------------------------------------------------
__device__ __forceinline__ void cp16(float* dst, const float* src) {
    unsigned d = (unsigned)__cvta_generic_to_shared(dst);
    asm volatile("cp.async.cg.shared.global [%0], [%1], 16;" :: "r"(d), "l"(src));
}

__device__ __forceinline__ void mma_tf32(float* d, const unsigned* a, const unsigned* b) {
    asm volatile("mma.sync.aligned.m16n8k8.row.col.f32.tf32.tf32.f32 "
                 "{%0,%1,%2,%3}, {%4,%5,%6,%7}, {%8,%9}, {%0,%1,%2,%3};"
                 : "+f"(d[0]), "+f"(d[1]), "+f"(d[2]), "+f"(d[3])
                 : "r"(a[0]), "r"(a[1]), "r"(a[2]), "r"(a[3]),
                   "r"(b[0]), "r"(b[1]));
}

__device__ __forceinline__ float gelu_tanh(float x) {
    return 0.5f * x * (1.f + tanhf(0.7978845608028654f * (x + 0.044715f * x * x * x)));
}

#define BFL 4608  // floats reserved for B tile per stage (max of 128*36, 32*132)

template <bool TRANSB, int BM>
__global__ void __launch_bounds__(256) gemm_tc_async(
    const float* __restrict__ A, int lda, long long saO, long long saI,
    const float* __restrict__ Bp, int ldb, long long sbO, long long sbI,
    float* __restrict__ C, int ldc, long long scO, long long scI,
    const float* __restrict__ R,
    int M, int N, int K, float alpha, int gelu_flag, int round_flag, int hdiv,
    MultiPtr P, int nmulti)
{
    constexpr int WM = BM / 32;
    constexpr int WN = 8 / WM;
    constexpr int WTN = 128 / WN;
    constexpr int NT = WTN / 8;
    constexpr int STAGE = BM * 36 + BFL;

    extern __shared__ float smf[];

    int z = blockIdx.z;
    if (nmulti > 1) {
        Bp = P.B[z];
        C = P.C[z];
    } else {
        int zo = z / hdiv, zi = z % hdiv;
        A  += (long long)zo * saO + (long long)zi * saI;
        Bp += (long long)zo * sbO + (long long)zi * sbI;
        long long co = (long long)zo * scO + (long long)zi * scI;
        C += co;
        if (R) R += co;
    }

    int tid = threadIdx.x;
    int warp = tid >> 5, lane = tid & 31;
    int g = lane >> 2, t = lane & 3;
    int mwarp = (warp % WM) * 32;
    int nwarp = (warp / WM) * WTN;
    int m0 = blockIdx.y * BM, n0 = blockIdx.x * 128;

    float acc[2][NT][4];
    #pragma unroll
    for (int i = 0; i < 2; i++)
        #pragma unroll
        for (int j = 0; j < NT; j++)
            #pragma unroll
            for (int r = 0; r < 4; r++) acc[i][j][r] = 0.f;

    const int KT = K >> 5;

    auto stage = [&](int kt, int sbuf) {
        float* Asf = smf + sbuf * STAGE;
        float* Bsf = Asf + BM * 36;
        int k0 = kt * 32;
        #pragma unroll
        for (int i = 0; i < BM / 32; i++) {
            int f = tid + i * 256;
            int row = f >> 3, ch = f & 7;
            cp16(Asf + row * 36 + ch * 4,
                 A + (long long)(m0 + row) * lda + k0 + ch * 4);
        }
        if (TRANSB) {
            #pragma unroll
            for (int i = 0; i < 4; i++) {
                int f = tid + i * 256;
                int row = f >> 3, ch = f & 7;
                cp16(Bsf + row * 36 + ch * 4,
                     Bp + (long long)(n0 + row) * ldb + k0 + ch * 4);
            }
        } else {
            #pragma unroll
            for (int i = 0; i < 4; i++) {
                int f = tid + i * 256;
                int kk = f >> 5, ch = f & 31;
                cp16(Bsf + kk * 132 + ch * 4,
                     Bp + (long long)(k0 + kk) * ldb + n0 + ch * 4);
            }
        }
        asm volatile("cp.async.commit_group;" ::: "memory");
    };

    for (int s = 0; s < PIPE - 1 && s < KT; s++) stage(s, s);

    for (int kt = 0; kt < KT; kt++) {
        if (kt == KT - 1) asm volatile("cp.async.wait_group 0;" ::: "memory");
        else              asm volatile("cp.async.wait_group %0;" :: "n"(PIPE - 2) : "memory");
        __syncthreads();

        int nk = kt + PIPE - 1;
        if (nk < KT) stage(nk, nk % PIPE);

        const unsigned* Asu = (const unsigned*)(smf + (kt % PIPE) * STAGE);
        const unsigned* Bsu = Asu + BM * 36;

        #pragma unroll
        for (int ks = 0; ks < 4; ks++) {
            int krow = ks * 8 + t;
            unsigned af[2][4];
            #pragma unroll
            for (int mt = 0; mt < 2; mt++) {
                int m = mwarp + mt * 16 + g;
                af[mt][0] = Asu[m * 36 + krow];
                af[mt][1] = Asu[(m + 8) * 36 + krow];
                af[mt][2] = Asu[m * 36 + krow + 4];
                af[mt][3] = Asu[(m + 8) * 36 + krow + 4];
            }
            unsigned bf[NT][2];
            #pragma unroll
            for (int nt = 0; nt < NT; nt++) {
                int n = nwarp + nt * 8 + g;
                if (TRANSB) {
                    bf[nt][0] = Bsu[n * 36 + krow];
                    bf[nt][1] = Bsu[n * 36 + krow + 4];
                } else {
                    bf[nt][0] = Bsu[krow * 132 + n];
                    bf[nt][1] = Bsu[(krow + 4) * 132 + n];
                }
            }
            #pragma unroll
            for (int mt = 0; mt < 2; mt++)
                #pragma unroll
                for (int nt = 0; nt < NT; nt++)
                    mma_tf32(acc[mt][nt], af[mt], bf[nt]);
        }
        __syncthreads();
    }

    // --- Epilogue
    #pragma unroll
    for (int mt = 0; mt < 2; mt++) {
        #pragma unroll
        for (int nt = 0; nt < NT; nt++) {
            #pragma unroll
            for (int r = 0; r < 4; r++) {
                int row = m0 + mwarp + mt * 16 + g + ((r & 2) ? 8 : 0);
                int col = n0 + nwarp + nt * 8 + t * 2 + (r & 1);
                if (row < M && col < N) {
                    float v = acc[mt][nt][r] * alpha;
                    if (R) v += R[(long long)row * ldc + col];
                    if (gelu_flag) v = gelu_tanh(v);
                    if (round_flag) v = roundtf(v);
                    C[(long long)row * ldc + col] = v;
                }
            }
        }
    }
}

// ---------------------------------------------------------------------------
// Causal softmax; probs rounded to tf32 (feed PV GEMM)
// ---------------------------------------------------------------------------
__global__ void softmax_causal_kernel(float* __restrict__ att) {
    long long idx = blockIdx.x;
    int i = (int)(idx % S_);
    float* row = att + idx * S_;
    int n = i + 1;

    __shared__ float red[256];
    float mx = -INFINITY;
    for (int j = threadIdx.x; j < n; j += 256) mx = fmaxf(mx, row[j]);
    red[threadIdx.x] = mx;
    __syncthreads();
    for (int o = 128; o > 0; o >>= 1) {
        if (threadIdx.x < o) red[threadIdx.x] = fmaxf(red[threadIdx.x], red[threadIdx.x + o]);
        __syncthreads();
    }
    mx = red[0];
    __syncthreads();

    float sum = 0.f;
    for (int j = threadIdx.x; j < n; j += 256) {
        float e = expf(row[j] - mx);
        row[j] = e;
        sum += e;
    }
    red[threadIdx.x] = sum;
    __syncthreads();
    for (int o = 128; o > 0; o >>= 1) {
        if (threadIdx.x < o) red[threadIdx.x] += red[threadIdx.x + o];
        __syncthreads();
    }
    float inv = 1.f / red[0];

    for (int j = threadIdx.x; j < n; j += 256) row[j] = roundtf(row[j] * inv);
    for (int j = n + threadIdx.x; j < S_; j += 256) row[j] = 0.f;
}

// ---------------------------------------------------------------------------
// Host launch helpers
// ---------------------------------------------------------------------------
template <bool TB, int BM>
static void run_gemm(dim3 grid,
                     const float* A, int lda, long long saO, long long saI,
                     const float* Bp, int ldb, long long sbO, long long sbI,
                     float* C, int ldc, long long scO, long long scI,
                     const float* R, int M, int N, int K,
                     float alpha, int gelu_flag, int round_flag, int hdiv,
                     MultiPtr mp, int nmulti)
{
    size_t smem = (size_t)PIPE * (BM * 36 + BFL) * sizeof(float);
    cudaFuncSetAttribute(gemm_tc_async<TB, BM>,
                         cudaFuncAttributeMaxDynamicSharedMemorySize, (int)smem);
    gemm_tc_async<TB, BM><<<grid, 256, smem>>>(A, lda, saO, saI, Bp, ldb, sbO, sbI,
                                               C, ldc, scO, scI, R, M, N, K,
                                               alpha, gelu_flag, round_flag, hdiv, mp, nmulti);
}

static void cvt_weights(const float* src, float* dst, long long n) {
    cvt_tf32_kernel<<<1184, 256>>>((const float4*)src, (float4*)dst, n >> 2);
}

extern "C" void kernel_launch(void* const* d_in, const int* in_sizes, int n_in,
                              void* d_out, int out_size) {
    const int*   tok         = (const int*)d_in[0];
    const float* tok_emb     = (const float*)d_in[1];
    const float* pos_emb     = (const float*)d_in[2];
    const float* pos_norm_w  = (const float*)d_in[3];
    const float* attn_norm_w = (const float*)d_in[4];
    const float* wq          = (const float*)d_in[5];
    const float* wk          = (const float*)d_in[6];
    const float* wv          = (const float*)d_in[7];
    const float* wo          = (const float*)d_in[8];
    const float* ffn_norm_w  = (const float*)d_in[9];
    const float* w1          = (const float*)d_in[10];
    const float* w2          = (const float*)d_in[11];
    const float* out_norm_w  = (const float*)d_in[12];
    const float* out_w       = (const float*)d_in[13];
    float* out = (float*)d_out;

    float *x, *xn, *q, *k, *v, *o, *att, *ffn;
    float *cwq, *cwk, *cwv, *cwo, *cw1, *cw2, *cow;
    cudaGetSymbolAddress((void**)&x,   g_x);
    cudaGetSymbolAddress((void**)&xn,  g_xn);
    cudaGetSymbolAddress((void**)&q,   g_q);
    cudaGetSymbolAddress((void**)&k,   g_k);
    cudaGetSymbolAddress((void**)&v,   g_v);
    cudaGetSymbolAddress((void**)&o,   g_o);
    cudaGetSymbolAddress((void**)&att, g_att);
    cudaGetSymbolAddress((void**)&ffn, g_ffn);
    cudaGetSymbolAddress((void**)&cwq, g_cwq);
    cudaGetSymbolAddress((void**)&cwk, g_cwk);
    cudaGetSymbolAddress((void**)&cwv, g_cwv);
    cudaGetSymbolAddress((void**)&cwo, g_cwo);
    cudaGetSymbolAddress((void**)&cw1, g_cw1);
    cudaGetSymbolAddress((void**)&cw2, g_cw2);
    cudaGetSymbolAddress((void**)&cow, g_cow);

    const float scale = 0.102062072615966f;  // 1/sqrt(96)
    const long long SS = (long long)S_ * S_;
    MultiPtr mp0 = {};

    // Pre-round weights to tf32 (exact tf32 values stored as fp32)
    cvt_weights(wq, cwq, (long long)L_ * D_ * D_);
    cvt_weights(wk, cwk, (long long)L_ * D_ * D_);
    cvt_weights(wv, cwv, (long long)L_ * D_ * D_);
    cvt_weights(wo, cwo, (long long)L_ * D_ * D_);
    cvt_weights(w1, cw1, (long long)L_ * D_ * F_);
    cvt_weights(w2, cw2, (long long)L_ * F_ * D_);
    cvt_weights(out_w, cow, (long long)D_ * V_);

    embed_norm_kernel<<<BS_, 256>>>(tok, tok_emb, pos_emb, pos_norm_w);

    for (int l = 0; l < L_; l++) {
        const float* lwq = cwq + (long long)l * D_ * D_;
        const float* lwk = cwk + (long long)l * D_ * D_;
        const float* lwv = cwv + (long long)l * D_ * D_;
        const float* lwo = cwo + (long long)l * D_ * D_;
        const float* lw1 = cw1 + (long long)l * D_ * F_;
        const float* lw2 = cw2 + (long long)l * F_ * D_;

        rmsnorm_kernel<<<BS_, 256>>>(x, xn, attn_norm_w + (long long)l * D_, D_);

        // fused QKV (outputs rounded: feed QK^T and PV MMAs)
        MultiPtr mq;
        mq.B[0] = lwq; mq.B[1] = lwk; mq.B[2] = lwv;
        mq.C[0] = q;   mq.C[1] = k;   mq.C[2] = v;
        run_gemm<false, 128>(dim3(6, 16, 3),
                             xn, D_, 0, 0, lwq, D_, 0, 0, q, D_, 0, 0,
                             nullptr, BS_, D_, D_, 1.f, 0, 1, 1, mq, 3);

        // scores[b,h] = scale * Q_h @ K_h^T
        run_gemm<true, 128>(dim3(8, 8, 16),
                            q, D_, (long long)S_ * D_, DH_,
                            k, D_, (long long)S_ * D_, DH_,
                            att, S_, (long long)H_ * SS, SS,
                            nullptr, S_, S_, DH_, scale, 0, 0, H_, mp0, 1);

        softmax_causal_kernel<<<B_ * H_ * S_, 256>>>(att);

        // o[b,:,h,:] = probs @ V_h  (output rounded: feeds o @ wo)
        run_gemm<false, 64>(dim3(1, 16, 16),
                            att, S_, (long long)H_ * SS, SS,
                            v, D_, (long long)S_ * D_, DH_,
                            o, D_, (long long)S_ * D_, DH_,
                            nullptr, S_, DH_, S_, 1.f, 0, 1, H_, mp0, 1);

        // x = x + o @ wo  (residual fp32, no rounding)
        run_gemm<false, 64>(dim3(6, 32, 1),
                            o, D_, 0, 0, lwo, D_, 0, 0, x, D_, 0, 0,
                            x, BS_, D_, D_, 1.f, 0, 0, 1, mp0, 1);

        rmsnorm_kernel<<<BS_, 256>>>(x, xn, ffn_norm_w + (long long)l * D_, D_);

        // ffn = round(gelu(xn @ w1))  (feeds w2 GEMM)
        run_gemm<false, 128>(dim3(16, 16, 1),
                             xn, D_, 0, 0, lw1, F_, 0, 0, ffn, F_, 0, 0,
                             nullptr, BS_, F_, D_, 1.f, 1, 1, 1, mp0, 1);

        // x = x + ffn @ w2
        run_gemm<false, 64>(dim3(6, 32, 1),
                            ffn, F_, 0, 0, lw2, D_, 0, 0, x, D_, 0, 0,
                            x, BS_, D_, F_, 1.f, 0, 0, 1, mp0, 1);
    }

    rmsnorm_kernel<<<BS_, 256>>>(x, xn, out_norm_w, D_);
    run_gemm<false, 128>(dim3(250, 16, 1),
                         xn, D_, 0, 0, cow, V_, 0, 0, out, V_, 0, 0,
                         nullptr, BS_, V_, D_, 1.f, 0, 0, 1, mp0, 1);
}